// round 11
// baseline (speedup 1.0000x reference)
#include <cuda_runtime.h>
#include <cuda_bf16.h>
#include <cstdint>

// Problem constants
#define G   7
#define BSZ 8
#define MSZ 512
#define NSZ 512
#define KSZ 1024
// x zp = -66, y zp = 160.  out = xs*ys * sum_k (x+66)*(y-160)
// x+66 in [-62,193], y-160 in [-160,95]: both EXACT in bf16 -> no corrections.

#define XELEMS ((size_t)G * BSZ * MSZ * KSZ)   // 29360128
#define YELEMS ((size_t)BSZ * KSZ * NSZ)       // 4194304

// ---- arch-specific feature gate (tcgen05 only legal on sm_103a pass) ----
#if defined(__CUDA_ARCH_FEAT_SM103_ALL) || \
    (defined(__CUDA_ARCH_SPECIFIC__) && (__CUDA_ARCH_SPECIFIC__ == 1030)) || \
    (defined(__CUDA_ARCH_FAMILY_SPECIFIC__) && (__CUDA_ARCH_FAMILY_SPECIFIC__ == 1030))
#define TC_OK 1
#endif

// ---------------- tcgen05 bf16 GEMM tiling ----------------
#define BMG 128
#define BNG 256
#define BKE 64              // K elems per stage
#define NSTG (KSZ / BKE)    // 16
// smem layout (byte offsets into dynamic smem)
#define SM_AB(b)  ((b) * 16384)               // A bf16 swizzled: 2 x 16KB
#define SM_BB(b)  (32768 + (b) * 32768)       // B bf16 swizzled: 2 x 32KB
#define SM_ST(b)  (98304 + (b) * 32768)       // A raw staging:   2 x 32KB
#define SM_TMEMP  163840
#define SM_MBAR0  163848
#define SM_MBAR1  163856
#define DSMEM_TC  163872

// Scratch (allocation-free: __device__ global)
__device__ __align__(16) uint16_t g_ytb[YELEMS];  // (y-160) transposed bf16 [b][n][k]

// ---------------------------------------------------------------------------
// helpers
// ---------------------------------------------------------------------------
__device__ __forceinline__ uint32_t smem_u32(const void* p) {
    uint32_t a;
    asm("{ .reg .u64 t; cvta.to.shared.u64 t, %1; cvt.u32.u64 %0, t; }" : "=r"(a) : "l"(p));
    return a;
}
__device__ __forceinline__ void cp16(uint32_t dst, const void* src) {
    asm volatile("cp.async.cg.shared.global [%0], [%1], 16;" :: "r"(dst), "l"(src));
}
__device__ __forceinline__ uint32_t pack_bf16(float lo, float hi) {
    __nv_bfloat162 h = __floats2bfloat162_rn(lo, hi);
    return *(uint32_t*)&h;
}

// ---------------------------------------------------------------------------
// Kernel 1: transpose y [b][k][n] -> g_ytb [b][n][k] = bf16(y - 160)
// (input-format probe inlined: int32-materialized vs raw bytes)
// ---------------------------------------------------------------------------
__global__ __launch_bounds__(256) void transpose_y_kernel(const void* __restrict__ yin) {
    __shared__ __align__(16) uint8_t s[32][136];
    int b  = blockIdx.z;
    int n0 = blockIdx.x * 128;
    int k0 = blockIdx.y * 32;
    int t  = threadIdx.x;

    // inline probe (uniform across block; y[0..7] is one hot L2 line)
    int fmt = 1;
    {
        const int* yi = (const int*)yin;
        #pragma unroll
        for (int j = 0; j < 8; j++) { int v = yi[j]; fmt &= (v >= 0 && v < 256); }
    }

    #pragma unroll
    for (int i = 0; i < 4; i++) {
        int w  = t + i * 256;
        int k  = w >> 5;
        int nw = w & 31;
        size_t base = ((size_t)(b * KSZ + k0 + k)) * NSZ + n0 + nw * 4;
        uint32_t wv;
        if (fmt) {
            int4 v = *(const int4*)((const int*)yin + base);
            wv = (v.x & 0xff) | ((v.y & 0xff) << 8) | ((v.z & 0xff) << 16) | ((uint32_t)(v.w & 0xff) << 24);
        } else {
            wv = *(const uint32_t*)((const uint8_t*)yin + base);
        }
        *(uint32_t*)&s[k][nw * 4] = wv;
    }
    __syncthreads();
    #pragma unroll
    for (int i = 0; i < 4; i++) {
        int w  = t + i * 256;
        int n  = w >> 3;
        int kq = w & 7;
        int e0 = (int)s[kq * 4 + 0][n] - 160;
        int e1 = (int)s[kq * 4 + 1][n] - 160;
        int e2 = (int)s[kq * 4 + 2][n] - 160;
        int e3 = (int)s[kq * 4 + 3][n] - 160;
        uint2 o;
        o.x = pack_bf16((float)e0, (float)e1);
        o.y = pack_bf16((float)e2, (float)e3);
        *(uint2*)(g_ytb + ((size_t)(b * NSZ + n0 + n)) * KSZ + k0 + kq * 4) = o;
    }
}

// ---------------------------------------------------------------------------
// Kernel 2: fused tcgen05 bf16 GEMM. A converted int32->bf16 IN-KERNEL via
// raw staging buffers (no separate repack pass). Tile 128(M) x 256(N).
// ---------------------------------------------------------------------------
#ifdef TC_OK
__device__ __forceinline__ uint32_t sw128(uint32_t off) { return off ^ ((off >> 3) & 0x70); }
__device__ __forceinline__ uint32_t elect_one() {
    uint32_t p;
    asm volatile("{\n\t.reg .pred P;\n\telect.sync _|P, 0xFFFFFFFF;\n\tselp.b32 %0, 1, 0, P;\n\t}" : "=r"(p));
    return p;
}
__device__ __forceinline__ void mbar_init(uint32_t a, uint32_t cnt) {
    asm volatile("mbarrier.init.shared.b64 [%0], %1;" :: "r"(a), "r"(cnt) : "memory");
}
__device__ __forceinline__ void mbar_wait(uint32_t a, uint32_t parity) {
    asm volatile(
        "{\n\t.reg .pred P;\n\t"
        "W%=:\n\t"
        "mbarrier.try_wait.parity.acquire.cta.shared::cta.b64 P, [%0], %1, 0x989680;\n\t"
        "@P bra D%=;\n\t"
        "bra W%=;\n\t"
        "D%=:\n\t}"
        :: "r"(a), "r"(parity) : "memory");
}
__device__ __forceinline__ uint64_t smem_desc(uint32_t addr) {
    const uint64_t base = (uint64_t(2) << 61) | (uint64_t(1) << 46) | (uint64_t(64) << 32) | (uint64_t(1) << 16);
    return base | ((uint64_t)(addr >> 4) & 0x3FFF);
}
#define IDESC_MAIN ((1u << 4) | (1u << 7) | (1u << 10) | ((BNG / 8) << 17) | ((BMG / 16) << 24))
__device__ __forceinline__ void mma_bf16(uint32_t d, uint64_t ad, uint64_t bd, uint32_t en) {
    asm volatile(
        "{\n\t.reg .pred p;\n\tsetp.ne.u32 p, %5, 0;\n\t"
        "tcgen05.mma.cta_group::1.kind::f16 [%0], %1, %2, %3, {%4, %4, %4, %4}, p;\n\t}"
        :: "r"(d), "l"(ad), "l"(bd), "r"((uint32_t)IDESC_MAIN), "r"(0u), "r"(en) : "memory");
}
#endif

__global__ __launch_bounds__(128, 1) void gemm_fused(const void* __restrict__ xin,
                                                     const float* __restrict__ xs,
                                                     const float* __restrict__ ys,
                                                     float* __restrict__ out) {
#ifdef TC_OK
    extern __shared__ __align__(1024) uint8_t smem[];
    const uint32_t sb = smem_u32(smem);
    const int t = threadIdx.x, wid = t >> 5, lane = t & 31;
    const int z = blockIdx.z, b = z & 7;
    const int m0 = blockIdx.y * BMG;
    const int n0 = blockIdx.x * BNG;

    // inline x-format probe (uniform)
    int fmt = 1;
    {
        const int* xi = (const int*)xin;
        #pragma unroll
        for (int j = 0; j < 8; j++) { int v = xi[j]; fmt &= (v >= -128 && v < 128); }
    }

    const size_t xbase = ((size_t)z * MSZ + m0) * KSZ;   // element offset of A tile
    const uint8_t* xa = (const uint8_t*)xin + xbase * (fmt ? 4 : 1);
    const uint16_t* yb = g_ytb + (size_t)b * NSZ * KSZ + (size_t)n0 * KSZ;

    auto loadstage = [&](int s, int buf) {
        uint32_t stb = sb + SM_ST(buf);
        uint32_t bbb = sb + SM_BB(buf);
        if (fmt) {
            // A raw int32: 128 rows x 256B
            #pragma unroll
            for (int i = 0; i < 16; i++) {
                int id = t + i * 128;
                int row = id >> 4, ch = id & 15;
                cp16(stb + row * 256 + ch * 16,
                     xa + ((size_t)row * KSZ + s * BKE + ch * 4) * 4);
            }
        } else {
            // A raw s8 bytes: 128 rows x 64B
            #pragma unroll
            for (int i = 0; i < 4; i++) {
                int id = t + i * 128;
                int row = id >> 2, ch = id & 3;
                cp16(stb + row * 64 + ch * 16,
                     xa + (size_t)row * KSZ + s * BKE + ch * 16);
            }
        }
        // B bf16 swizzled: 256 rows x 128B
        #pragma unroll
        for (int i = 0; i < 16; i++) {
            int id = t + i * 128;
            int row = id >> 3, c = (id & 7) << 4;
            cp16(bbb + sw128(row * 128 + c),
                 (const uint8_t*)(yb + (size_t)row * KSZ) + s * 128 + c);
        }
        asm volatile("cp.async.commit_group;" ::: "memory");
    };

    // convert staging(buf) -> swizzled bf16 A(buf). Conflict-free LDS/STS.
    auto convertA = [&](int buf) {
        const uint8_t* stp = smem + SM_ST(buf);
        uint8_t* abp = smem + SM_AB(buf);
        if (fmt) {
            #pragma unroll
            for (int i = 0; i < 16; i++) {
                int blk = i * 4 + wid;                 // 0..63 (2 rows each)
                int4 v = *(const int4*)(stp + blk * 512 + lane * 16);
                int row = blk * 2 + (lane >> 4);
                int e8  = (lane & 15) * 8;             // byte offset in bf16 row
                uint2 o;
                o.x = pack_bf16((float)(v.x + 66), (float)(v.y + 66));
                o.y = pack_bf16((float)(v.z + 66), (float)(v.w + 66));
                *(uint2*)(abp + sw128(row * 128 + e8)) = o;
            }
        } else {
            #pragma unroll
            for (int i = 0; i < 4; i++) {
                int blk = i * 4 + wid;                 // 0..15 (8 rows each)
                int4 v = *(const int4*)(stp + blk * 512 + lane * 16);
                int row = blk * 8 + (lane >> 2);
                int e  = (lane & 3) * 16;              // elem base in row
                uint32_t w[4] = {(uint32_t)v.x, (uint32_t)v.y, (uint32_t)v.z, (uint32_t)v.w};
                uint4 o0;
                o0.x = pack_bf16((float)((int)(int8_t)(w[0]) + 66), (float)((int)(int8_t)(w[0] >> 8) + 66));
                o0.y = pack_bf16((float)((int)(int8_t)(w[0] >> 16) + 66), (float)((int)(int8_t)(w[0] >> 24) + 66));
                o0.z = pack_bf16((float)((int)(int8_t)(w[1]) + 66), (float)((int)(int8_t)(w[1] >> 8) + 66));
                o0.w = pack_bf16((float)((int)(int8_t)(w[1] >> 16) + 66), (float)((int)(int8_t)(w[1] >> 24) + 66));
                *(uint4*)(abp + sw128(row * 128 + e * 2)) = o0;
                uint4 o1;
                o1.x = pack_bf16((float)((int)(int8_t)(w[2]) + 66), (float)((int)(int8_t)(w[2] >> 8) + 66));
                o1.y = pack_bf16((float)((int)(int8_t)(w[2] >> 16) + 66), (float)((int)(int8_t)(w[2] >> 24) + 66));
                o1.z = pack_bf16((float)((int)(int8_t)(w[3]) + 66), (float)((int)(int8_t)(w[3] >> 8) + 66));
                o1.w = pack_bf16((float)((int)(int8_t)(w[3] >> 16) + 66), (float)((int)(int8_t)(w[3] >> 24) + 66));
                *(uint4*)(abp + sw128(row * 128 + e * 2 + 16)) = o1;
            }
        }
    };

    // issue first stage BEFORE the TMEM alloc
    loadstage(0, 0);

    if (wid == 0) {
        asm volatile("tcgen05.alloc.cta_group::1.sync.aligned.shared::cta.b32 [%0], %1;"
                     :: "r"(sb + SM_TMEMP), "r"(256u) : "memory");
        asm volatile("tcgen05.relinquish_alloc_permit.cta_group::1.sync.aligned;" ::: "memory");
    }
    if (t == 0) { mbar_init(sb + SM_MBAR0, 1); mbar_init(sb + SM_MBAR1, 1); }
    __syncthreads();
    uint32_t tmem;
    asm volatile("ld.shared.b32 %0, [%1];" : "=r"(tmem) : "r"(sb + SM_TMEMP));

    int ph0 = 0, ph1 = 0;

    for (int s = 0; s < NSTG; s++) {
        const int buf = s & 1;
        if (s + 1 < NSTG) {
            const int nb = buf ^ 1;
            if (s + 1 >= 2) {    // bufs nb freed when MMA(s-1) completes
                if (nb == 0) { mbar_wait(sb + SM_MBAR0, ph0); ph0 ^= 1; }
                else         { mbar_wait(sb + SM_MBAR1, ph1); ph1 ^= 1; }
            }
            loadstage(s + 1, nb);
            asm volatile("cp.async.wait_group 1;" ::: "memory");   // stage s arrived
        } else {
            asm volatile("cp.async.wait_group 0;" ::: "memory");
        }
        __syncthreads();                 // staging(s) visible to all threads
        convertA(buf);                   // staging -> swizzled bf16 A
        __syncthreads();                 // conversion visible
        asm volatile("fence.proxy.async.shared::cta;" ::: "memory");

        if (wid == 0) {
            asm volatile("tcgen05.fence::after_thread_sync;" ::: "memory");
            if (elect_one()) {
                uint64_t ad = smem_desc(sb + SM_AB(buf));
                uint64_t bd = smem_desc(sb + SM_BB(buf));
                #pragma unroll
                for (int k = 0; k < 4; k++) {   // 4 x K=16 per stage
                    mma_bf16(tmem, ad + k * 2, bd + k * 2, (uint32_t)(s * 4 + k));
                }
                asm volatile("tcgen05.commit.cta_group::1.mbarrier::arrive::one.shared::cluster.b64 [%0];"
                             :: "r"(sb + (buf ? SM_MBAR1 : SM_MBAR0)) : "memory");
            }
        }
    }

    // stage 15 committed to mbar1; covers all prior mma
    mbar_wait(sb + SM_MBAR1, ph1);
    asm volatile("tcgen05.fence::after_thread_sync;" ::: "memory");
    __syncthreads();

    const float sc = xs[0] * ys[0];
    float* tile = (float*)(smem + SM_ST(0) + wid * 4352);   // per-warp 32x33 tile

    #pragma unroll 1
    for (int chunk = 0; chunk < BNG / 32; chunk++) {
        uint32_t d[32];
        asm volatile(
            "tcgen05.ld.sync.aligned.32x32b.x32.b32 "
            "{%0,%1,%2,%3,%4,%5,%6,%7,%8,%9,%10,%11,%12,%13,%14,%15,"
            "%16,%17,%18,%19,%20,%21,%22,%23,%24,%25,%26,%27,%28,%29,%30,%31}, [%32];"
            : "=r"(d[0]), "=r"(d[1]), "=r"(d[2]), "=r"(d[3]), "=r"(d[4]), "=r"(d[5]), "=r"(d[6]), "=r"(d[7]),
              "=r"(d[8]), "=r"(d[9]), "=r"(d[10]), "=r"(d[11]), "=r"(d[12]), "=r"(d[13]), "=r"(d[14]), "=r"(d[15]),
              "=r"(d[16]), "=r"(d[17]), "=r"(d[18]), "=r"(d[19]), "=r"(d[20]), "=r"(d[21]), "=r"(d[22]), "=r"(d[23]),
              "=r"(d[24]), "=r"(d[25]), "=r"(d[26]), "=r"(d[27]), "=r"(d[28]), "=r"(d[29]), "=r"(d[30]), "=r"(d[31])
            : "r"(tmem + chunk * 32));
        asm volatile("tcgen05.wait::ld.sync.aligned;" ::: "memory");

        #pragma unroll
        for (int c = 0; c < 32; c++) {
            tile[lane * 33 + c] = sc * __uint_as_float(d[c]);
        }
        __syncwarp();
        #pragma unroll
        for (int r = 0; r < 32; r++) {
            out[((size_t)z * MSZ + m0 + wid * 32 + r) * NSZ + n0 + chunk * 32 + lane] = tile[r * 33 + lane];
        }
        __syncwarp();
    }

    __syncthreads();
    if (wid == 0) {
        asm volatile("tcgen05.dealloc.cta_group::1.sync.aligned.b32 %0, %1;" :: "r"(tmem), "r"(256u));
    }
#endif
}

// ---------------------------------------------------------------------------
extern "C" void kernel_launch(void* const* d_in, const int* in_sizes, int n_in,
                              void* d_out, int out_size) {
    const void* x = nullptr;
    const void* y = nullptr;
    const float* xs = nullptr;
    const float* ys = nullptr;

    for (int i = 0; i < n_in; i++) {
        long sz = in_sizes[i];
        if (sz == (long)XELEMS) x = d_in[i];
        else if (sz == (long)YELEMS) y = d_in[i];
        else if (xs == nullptr) xs = (const float*)d_in[i];
        else if (ys == nullptr) ys = (const float*)d_in[i];
    }
    float* out = (float*)d_out;

    cudaFuncSetAttribute(gemm_fused, cudaFuncAttributeMaxDynamicSharedMemorySize, DSMEM_TC);

    transpose_y_kernel<<<dim3(NSZ / 128, KSZ / 32, BSZ), 256>>>(y);
    gemm_fused<<<dim3(NSZ / BNG, MSZ / BMG, G * BSZ), 128, DSMEM_TC>>>(x, xs, ys, out);
}

// round 12
// speedup vs baseline: 1.4642x; 1.4642x over previous
#include <cuda_runtime.h>
#include <cuda_bf16.h>
#include <cstdint>

// Problem constants
#define G   7
#define BSZ 8
#define MSZ 512
#define NSZ 512
#define KSZ 1024
// x zp = -66, y zp = 160.  out = xs*ys * sum_k (x+66)*(y-160)
// x+66 in [-62,193], y-160 in [-160,95]: both EXACT in bf16 -> no corrections.

#define XELEMS ((size_t)G * BSZ * MSZ * KSZ)   // 29360128
#define YELEMS ((size_t)BSZ * KSZ * NSZ)       // 4194304

// ---- arch-specific feature gate (tcgen05 only legal on sm_103a pass) ----
#if defined(__CUDA_ARCH_FEAT_SM103_ALL) || \
    (defined(__CUDA_ARCH_SPECIFIC__) && (__CUDA_ARCH_SPECIFIC__ == 1030)) || \
    (defined(__CUDA_ARCH_FAMILY_SPECIFIC__) && (__CUDA_ARCH_FAMILY_SPECIFIC__ == 1030))
#define TC_OK 1
#endif

// ---------------- tcgen05 bf16 GEMM tiling ----------------
#define BMG 128
#define BNG 256
#define BKE 64              // K elems per stage
#define NSTG (KSZ / BKE)    // 16
// smem layout (byte offsets): A bf16 2x16KB, B bf16 2x32KB  -> 96KB, 2 CTAs/SM
#define SM_AB(b)  ((b) * 16384)
#define SM_BB(b)  (32768 + (b) * 32768)
#define SM_TMEMP  98304
#define SM_MBAR0  98312
#define SM_MBAR1  98320
#define DSMEM_TC  98336

// Scratch (allocation-free: __device__ global)
__device__ __align__(16) uint16_t g_ytb[YELEMS];  // (y-160) transposed bf16 [b][n][k]

// ---------------------------------------------------------------------------
// helpers
// ---------------------------------------------------------------------------
__device__ __forceinline__ uint32_t smem_u32(const void* p) {
    uint32_t a;
    asm("{ .reg .u64 t; cvta.to.shared.u64 t, %1; cvt.u32.u64 %0, t; }" : "=r"(a) : "l"(p));
    return a;
}
__device__ __forceinline__ void cp16(uint32_t dst, const void* src) {
    asm volatile("cp.async.cg.shared.global [%0], [%1], 16;" :: "r"(dst), "l"(src));
}
__device__ __forceinline__ uint32_t pack_bf16(float lo, float hi) {
    __nv_bfloat162 h = __floats2bfloat162_rn(lo, hi);
    return *(uint32_t*)&h;
}

// ---------------------------------------------------------------------------
// Kernel 1: transpose y [b][k][n] -> g_ytb [b][n][k] = bf16(y - 160)
// (input-format probe inlined: int32-materialized vs raw bytes)
// ---------------------------------------------------------------------------
__global__ __launch_bounds__(256) void transpose_y_kernel(const void* __restrict__ yin) {
    __shared__ __align__(16) uint8_t s[32][136];
    int b  = blockIdx.z;
    int n0 = blockIdx.x * 128;
    int k0 = blockIdx.y * 32;
    int t  = threadIdx.x;

    int fmt = 1;
    {
        const int* yi = (const int*)yin;
        #pragma unroll
        for (int j = 0; j < 8; j++) { int v = yi[j]; fmt &= (v >= 0 && v < 256); }
    }

    #pragma unroll
    for (int i = 0; i < 4; i++) {
        int w  = t + i * 256;
        int k  = w >> 5;
        int nw = w & 31;
        size_t base = ((size_t)(b * KSZ + k0 + k)) * NSZ + n0 + nw * 4;
        uint32_t wv;
        if (fmt) {
            int4 v = *(const int4*)((const int*)yin + base);
            wv = (v.x & 0xff) | ((v.y & 0xff) << 8) | ((v.z & 0xff) << 16) | ((uint32_t)(v.w & 0xff) << 24);
        } else {
            wv = *(const uint32_t*)((const uint8_t*)yin + base);
        }
        *(uint32_t*)&s[k][nw * 4] = wv;
    }
    __syncthreads();
    #pragma unroll
    for (int i = 0; i < 4; i++) {
        int w  = t + i * 256;
        int n  = w >> 3;
        int kq = w & 7;
        int e0 = (int)s[kq * 4 + 0][n] - 160;
        int e1 = (int)s[kq * 4 + 1][n] - 160;
        int e2 = (int)s[kq * 4 + 2][n] - 160;
        int e3 = (int)s[kq * 4 + 3][n] - 160;
        uint2 o;
        o.x = pack_bf16((float)e0, (float)e1);
        o.y = pack_bf16((float)e2, (float)e3);
        *(uint2*)(g_ytb + ((size_t)(b * NSZ + n0 + n)) * KSZ + k0 + kq * 4) = o;
    }
}

// ---------------------------------------------------------------------------
// Kernel 2: fused tcgen05 bf16 GEMM. A converted int32->bf16 in REGISTERS
// (LDG -> cvt -> STS swizzled), no staging smem -> 96KB -> 2 CTAs/SM.
// Tile 128(M) x 256(N), 256 threads.
// ---------------------------------------------------------------------------
#ifdef TC_OK
__device__ __forceinline__ uint32_t sw128(uint32_t off) { return off ^ ((off >> 3) & 0x70); }
__device__ __forceinline__ uint32_t elect_one() {
    uint32_t p;
    asm volatile("{\n\t.reg .pred P;\n\telect.sync _|P, 0xFFFFFFFF;\n\tselp.b32 %0, 1, 0, P;\n\t}" : "=r"(p));
    return p;
}
__device__ __forceinline__ void mbar_init(uint32_t a, uint32_t cnt) {
    asm volatile("mbarrier.init.shared.b64 [%0], %1;" :: "r"(a), "r"(cnt) : "memory");
}
__device__ __forceinline__ void mbar_wait(uint32_t a, uint32_t parity) {
    asm volatile(
        "{\n\t.reg .pred P;\n\t"
        "W%=:\n\t"
        "mbarrier.try_wait.parity.acquire.cta.shared::cta.b64 P, [%0], %1, 0x989680;\n\t"
        "@P bra D%=;\n\t"
        "bra W%=;\n\t"
        "D%=:\n\t}"
        :: "r"(a), "r"(parity) : "memory");
}
__device__ __forceinline__ uint64_t smem_desc(uint32_t addr) {
    const uint64_t base = (uint64_t(2) << 61) | (uint64_t(1) << 46) | (uint64_t(64) << 32) | (uint64_t(1) << 16);
    return base | ((uint64_t)(addr >> 4) & 0x3FFF);
}
#define IDESC_MAIN ((1u << 4) | (1u << 7) | (1u << 10) | ((BNG / 8) << 17) | ((BMG / 16) << 24))
__device__ __forceinline__ void mma_bf16(uint32_t d, uint64_t ad, uint64_t bd, uint32_t en) {
    asm volatile(
        "{\n\t.reg .pred p;\n\tsetp.ne.u32 p, %5, 0;\n\t"
        "tcgen05.mma.cta_group::1.kind::f16 [%0], %1, %2, %3, {%4, %4, %4, %4}, p;\n\t}"
        :: "r"(d), "l"(ad), "l"(bd), "r"((uint32_t)IDESC_MAIN), "r"(0u), "r"(en) : "memory");
}
#endif

__global__ __launch_bounds__(256, 2) void gemm_fused(const void* __restrict__ xin,
                                                     const float* __restrict__ xs,
                                                     const float* __restrict__ ys,
                                                     float* __restrict__ out) {
#ifdef TC_OK
    extern __shared__ __align__(1024) uint8_t smem[];
    const uint32_t sb = smem_u32(smem);
    const int t = threadIdx.x, wid = t >> 5, lane = t & 31;
    const int z = blockIdx.z, b = z & 7;
    const int m0 = blockIdx.y * BMG;
    const int n0 = blockIdx.x * BNG;

    // inline x-format probe (uniform across block)
    int fmt = 1;
    {
        const int* xi = (const int*)xin;
        #pragma unroll
        for (int j = 0; j < 8; j++) { int v = xi[j]; fmt &= (v >= -128 && v < 128); }
    }

    // this thread's A slice: row = t>>1, K-half = t&1 (32 elems per stage)
    const int arow = t >> 1, ahalf = t & 1;
    const size_t arow_elem = ((size_t)z * MSZ + m0 + arow) * KSZ;
    const uint16_t* ybp = g_ytb + (size_t)b * NSZ * KSZ + (size_t)n0 * KSZ;

    int4 r[8];   // A register staging (int32: 8 int4 = 32 elems; s8: r[0..1])

    auto ldgA = [&](int s) {
        if (fmt) {
            const int4* p = (const int4*)xin + (arow_elem + s * BKE + ahalf * 32) / 4;
            #pragma unroll
            for (int i = 0; i < 8; i++) r[i] = p[i];
        } else {
            const int4* p = (const int4*)((const uint8_t*)xin + arow_elem + s * BKE + ahalf * 32);
            r[0] = p[0]; r[1] = p[1];
        }
    };
    auto stsA = [&](int buf) {
        uint8_t* abp = smem + SM_AB(buf);
        if (fmt) {
            #pragma unroll
            for (int j = 0; j < 4; j++) {
                int4 a = r[2 * j], c = r[2 * j + 1];
                uint4 o;
                o.x = pack_bf16((float)(a.x + 66), (float)(a.y + 66));
                o.y = pack_bf16((float)(a.z + 66), (float)(a.w + 66));
                o.z = pack_bf16((float)(c.x + 66), (float)(c.y + 66));
                o.w = pack_bf16((float)(c.z + 66), (float)(c.w + 66));
                *(uint4*)(abp + sw128(arow * 128 + (ahalf * 4 + j) * 16)) = o;
            }
        } else {
            #pragma unroll
            for (int j = 0; j < 4; j++) {
                uint32_t w0 = (j < 2) ? ((j & 1) ? (uint32_t)r[0].z : (uint32_t)r[0].x)
                                      : ((j & 1) ? (uint32_t)r[1].z : (uint32_t)r[1].x);
                uint32_t w1 = (j < 2) ? ((j & 1) ? (uint32_t)r[0].w : (uint32_t)r[0].y)
                                      : ((j & 1) ? (uint32_t)r[1].w : (uint32_t)r[1].y);
                uint4 o;
                o.x = pack_bf16((float)((int)(int8_t)(w0) + 66), (float)((int)(int8_t)(w0 >> 8) + 66));
                o.y = pack_bf16((float)((int)(int8_t)(w0 >> 16) + 66), (float)((int)(int8_t)(w0 >> 24) + 66));
                o.z = pack_bf16((float)((int)(int8_t)(w1) + 66), (float)((int)(int8_t)(w1 >> 8) + 66));
                o.w = pack_bf16((float)((int)(int8_t)(w1 >> 16) + 66), (float)((int)(int8_t)(w1 >> 24) + 66));
                *(uint4*)(abp + sw128(arow * 128 + (ahalf * 4 + j) * 16)) = o;
            }
        }
    };
    auto loadB = [&](int s, int buf) {
        uint32_t bbb = sb + SM_BB(buf);
        #pragma unroll
        for (int i = 0; i < 8; i++) {          // 256 rows x 128B = 2048 chunks / 256 thr
            int id = t + i * 256;
            int row = id >> 3, c = (id & 7) << 4;
            cp16(bbb + sw128(row * 128 + c),
                 (const uint8_t*)(ybp + (size_t)row * KSZ) + s * 128 + c);
        }
        asm volatile("cp.async.commit_group;" ::: "memory");
    };

    // prologue: A regs + B stage 0 in flight BEFORE (possibly blocking) alloc
    ldgA(0);
    loadB(0, 0);

    if (wid == 0) {
        asm volatile("tcgen05.alloc.cta_group::1.sync.aligned.shared::cta.b32 [%0], %1;"
                     :: "r"(sb + SM_TMEMP), "r"(256u) : "memory");
        asm volatile("tcgen05.relinquish_alloc_permit.cta_group::1.sync.aligned;" ::: "memory");
    }
    if (t == 0) { mbar_init(sb + SM_MBAR0, 1); mbar_init(sb + SM_MBAR1, 1); }
    __syncthreads();
    uint32_t tmem;
    asm volatile("ld.shared.b32 %0, [%1];" : "=r"(tmem) : "r"(sb + SM_TMEMP));

    int ph0 = 0, ph1 = 0;

    for (int s = 0; s < NSTG; s++) {
        const int buf = s & 1;
        if (s + 1 < NSTG) {
            const int nb = buf ^ 1;
            if (s + 1 >= 2) {    // nb freed when MMA(s-1) completes
                if (nb == 0) { mbar_wait(sb + SM_MBAR0, ph0); ph0 ^= 1; }
                else         { mbar_wait(sb + SM_MBAR1, ph1); ph1 ^= 1; }
            }
            loadB(s + 1, nb);
            asm volatile("cp.async.wait_group 1;" ::: "memory");   // B(s) arrived
        } else {
            asm volatile("cp.async.wait_group 0;" ::: "memory");
        }
        stsA(buf);                       // regs(s) -> swizzled bf16 A(buf)
        if (s + 1 < NSTG) ldgA(s + 1);   // prefetch next A into regs
        __syncthreads();                 // A STS + B visible to all
        asm volatile("fence.proxy.async.shared::cta;" ::: "memory");

        if (wid == 0) {
            asm volatile("tcgen05.fence::after_thread_sync;" ::: "memory");
            if (elect_one()) {
                uint64_t ad = smem_desc(sb + SM_AB(buf));
                uint64_t bd = smem_desc(sb + SM_BB(buf));
                #pragma unroll
                for (int k = 0; k < 4; k++) {   // 4 x K=16 per stage
                    mma_bf16(tmem, ad + k * 2, bd + k * 2, (uint32_t)(s * 4 + k));
                }
                asm volatile("tcgen05.commit.cta_group::1.mbarrier::arrive::one.shared::cluster.b64 [%0];"
                             :: "r"(sb + (buf ? SM_MBAR1 : SM_MBAR0)) : "memory");
            }
        }
    }

    // stage 15 committed to mbar1; covers all prior mma
    mbar_wait(sb + SM_MBAR1, ph1);
    asm volatile("tcgen05.fence::after_thread_sync;" ::: "memory");
    __syncthreads();

    // epilogue over all 8 warps: warp w reads TMEM subpartition (w&3),
    // column chunks (w>>2)*4 .. +3
    const float sc = xs[0] * ys[0];
    float* tile = (float*)(smem + wid * 4352);   // 8 x 32x33 f32 tiles (34.8KB)
    const int part = wid & 3;
    const int cbase = (wid >> 2) * 4;

    #pragma unroll 1
    for (int ci = 0; ci < 4; ci++) {
        const int chunk = cbase + ci;
        uint32_t d[32];
        asm volatile(
            "tcgen05.ld.sync.aligned.32x32b.x32.b32 "
            "{%0,%1,%2,%3,%4,%5,%6,%7,%8,%9,%10,%11,%12,%13,%14,%15,"
            "%16,%17,%18,%19,%20,%21,%22,%23,%24,%25,%26,%27,%28,%29,%30,%31}, [%32];"
            : "=r"(d[0]), "=r"(d[1]), "=r"(d[2]), "=r"(d[3]), "=r"(d[4]), "=r"(d[5]), "=r"(d[6]), "=r"(d[7]),
              "=r"(d[8]), "=r"(d[9]), "=r"(d[10]), "=r"(d[11]), "=r"(d[12]), "=r"(d[13]), "=r"(d[14]), "=r"(d[15]),
              "=r"(d[16]), "=r"(d[17]), "=r"(d[18]), "=r"(d[19]), "=r"(d[20]), "=r"(d[21]), "=r"(d[22]), "=r"(d[23]),
              "=r"(d[24]), "=r"(d[25]), "=r"(d[26]), "=r"(d[27]), "=r"(d[28]), "=r"(d[29]), "=r"(d[30]), "=r"(d[31])
            : "r"(tmem + chunk * 32));
        asm volatile("tcgen05.wait::ld.sync.aligned;" ::: "memory");

        #pragma unroll
        for (int c = 0; c < 32; c++) {
            tile[lane * 33 + c] = sc * __uint_as_float(d[c]);
        }
        __syncwarp();
        #pragma unroll
        for (int rr = 0; rr < 32; rr++) {
            out[((size_t)z * MSZ + m0 + part * 32 + rr) * NSZ + n0 + chunk * 32 + lane] = tile[rr * 33 + lane];
        }
        __syncwarp();
    }

    __syncthreads();
    if (wid == 0) {
        asm volatile("tcgen05.dealloc.cta_group::1.sync.aligned.b32 %0, %1;" :: "r"(tmem), "r"(256u));
    }
#endif
}

// ---------------------------------------------------------------------------
extern "C" void kernel_launch(void* const* d_in, const int* in_sizes, int n_in,
                              void* d_out, int out_size) {
    const void* x = nullptr;
    const void* y = nullptr;
    const float* xs = nullptr;
    const float* ys = nullptr;

    for (int i = 0; i < n_in; i++) {
        long sz = in_sizes[i];
        if (sz == (long)XELEMS) x = d_in[i];
        else if (sz == (long)YELEMS) y = d_in[i];
        else if (xs == nullptr) xs = (const float*)d_in[i];
        else if (ys == nullptr) ys = (const float*)d_in[i];
    }
    float* out = (float*)d_out;

    cudaFuncSetAttribute(gemm_fused, cudaFuncAttributeMaxDynamicSharedMemorySize, DSMEM_TC);

    transpose_y_kernel<<<dim3(NSZ / 128, KSZ / 32, BSZ), 256>>>(y);
    gemm_fused<<<dim3(NSZ / BNG, MSZ / BMG, G * BSZ), 256, DSMEM_TC>>>(x, xs, ys, out);
}

// round 15
// speedup vs baseline: 2.1384x; 1.4604x over previous
#include <cuda_runtime.h>
#include <cuda_bf16.h>
#include <cstdint>

// Problem constants
#define G   7
#define BSZ 8
#define MSZ 512
#define NSZ 512
#define KSZ 1024
// x zp = -66, y zp = 160.  out = xs*ys * sum_k (x+66)*(y-160)
// x+66 in [-62,193], y-160 in [-160,95]: both EXACT in bf16 -> no corrections.

#define XELEMS ((size_t)G * BSZ * MSZ * KSZ)   // 29360128
#define YELEMS ((size_t)BSZ * KSZ * NSZ)       // 4194304

// ---- arch-specific feature gate (tcgen05 only legal on sm_103a pass) ----
#if defined(__CUDA_ARCH_FEAT_SM103_ALL) || \
    (defined(__CUDA_ARCH_SPECIFIC__) && (__CUDA_ARCH_SPECIFIC__ == 1030)) || \
    (defined(__CUDA_ARCH_FAMILY_SPECIFIC__) && (__CUDA_ARCH_FAMILY_SPECIFIC__ == 1030))
#define TC_OK 1
#endif

// ---------------- tcgen05 bf16 GEMM tiling ----------------
#define BMG 128
#define BNG 256
#define BKE 64              // K elems per stage
#define NSTG (KSZ / BKE)    // 16
// smem layout (byte offsets): A bf16 2x16KB, B bf16 2x32KB  -> 96KB, 2 CTAs/SM
#define SM_AB(b)  ((b) * 16384)
#define SM_BB(b)  (32768 + (b) * 32768)
#define SM_TMEMP  98304
#define SM_MBAR0  98312
#define SM_MBAR1  98320
#define DSMEM_TC  98336

// Scratch (allocation-free: __device__ global)
__device__ __align__(16) uint16_t g_ytb[YELEMS];  // (y-160) transposed bf16 [b][n][k]

// ---------------------------------------------------------------------------
// helpers
// ---------------------------------------------------------------------------
__device__ __forceinline__ uint32_t smem_u32(const void* p) {
    uint32_t a;
    asm("{ .reg .u64 t; cvta.to.shared.u64 t, %1; cvt.u32.u64 %0, t; }" : "=r"(a) : "l"(p));
    return a;
}
__device__ __forceinline__ void cp16(uint32_t dst, const void* src) {
    asm volatile("cp.async.cg.shared.global [%0], [%1], 16;" :: "r"(dst), "l"(src));
}
__device__ __forceinline__ uint32_t pack_bf16(float lo, float hi) {
    __nv_bfloat162 h = __floats2bfloat162_rn(lo, hi);
    return *(uint32_t*)&h;
}

// ---------------------------------------------------------------------------
// Kernel 1: transpose y [b][k][n] -> g_ytb [b][n][k] = bf16(y - 160)
// (input-format probe inlined: int32-materialized vs raw bytes)
// ---------------------------------------------------------------------------
__global__ __launch_bounds__(256) void transpose_y_kernel(const void* __restrict__ yin) {
    __shared__ __align__(16) uint8_t s[32][136];
    int b  = blockIdx.z;
    int n0 = blockIdx.x * 128;
    int k0 = blockIdx.y * 32;
    int t  = threadIdx.x;

    int fmt = 1;
    {
        const int* yi = (const int*)yin;
        #pragma unroll
        for (int j = 0; j < 8; j++) { int v = yi[j]; fmt &= (v >= 0 && v < 256); }
    }

    #pragma unroll
    for (int i = 0; i < 4; i++) {
        int w  = t + i * 256;
        int k  = w >> 5;
        int nw = w & 31;
        size_t base = ((size_t)(b * KSZ + k0 + k)) * NSZ + n0 + nw * 4;
        uint32_t wv;
        if (fmt) {
            int4 v = *(const int4*)((const int*)yin + base);
            wv = (v.x & 0xff) | ((v.y & 0xff) << 8) | ((v.z & 0xff) << 16) | ((uint32_t)(v.w & 0xff) << 24);
        } else {
            wv = *(const uint32_t*)((const uint8_t*)yin + base);
        }
        *(uint32_t*)&s[k][nw * 4] = wv;
    }
    __syncthreads();
    #pragma unroll
    for (int i = 0; i < 4; i++) {
        int w  = t + i * 256;
        int n  = w >> 3;
        int kq = w & 7;
        int e0 = (int)s[kq * 4 + 0][n] - 160;
        int e1 = (int)s[kq * 4 + 1][n] - 160;
        int e2 = (int)s[kq * 4 + 2][n] - 160;
        int e3 = (int)s[kq * 4 + 3][n] - 160;
        uint2 o;
        o.x = pack_bf16((float)e0, (float)e1);
        o.y = pack_bf16((float)e2, (float)e3);
        *(uint2*)(g_ytb + ((size_t)(b * NSZ + n0 + n)) * KSZ + k0 + kq * 4) = o;
    }
}

// ---------------------------------------------------------------------------
// Kernel 2: fused tcgen05 bf16 GEMM. A converted int32->bf16 in REGISTERS.
// COALESCED A loads: warp w owns rows 16w..16w+15; per LDG inst the 32 lanes
// cover 2 rows x 256 contiguous bytes -> 4 fully-used lines (ideal wavefronts).
// ---------------------------------------------------------------------------
#ifdef TC_OK
__device__ __forceinline__ uint32_t sw128(uint32_t off) { return off ^ ((off >> 3) & 0x70); }
__device__ __forceinline__ uint32_t elect_one() {
    uint32_t p;
    asm volatile("{\n\t.reg .pred P;\n\telect.sync _|P, 0xFFFFFFFF;\n\tselp.b32 %0, 1, 0, P;\n\t}" : "=r"(p));
    return p;
}
__device__ __forceinline__ void mbar_init(uint32_t a, uint32_t cnt) {
    asm volatile("mbarrier.init.shared.b64 [%0], %1;" :: "r"(a), "r"(cnt) : "memory");
}
__device__ __forceinline__ void mbar_wait(uint32_t a, uint32_t parity) {
    asm volatile(
        "{\n\t.reg .pred P;\n\t"
        "W%=:\n\t"
        "mbarrier.try_wait.parity.acquire.cta.shared::cta.b64 P, [%0], %1, 0x989680;\n\t"
        "@P bra D%=;\n\t"
        "bra W%=;\n\t"
        "D%=:\n\t}"
        :: "r"(a), "r"(parity) : "memory");
}
__device__ __forceinline__ uint64_t smem_desc(uint32_t addr) {
    const uint64_t base = (uint64_t(2) << 61) | (uint64_t(1) << 46) | (uint64_t(64) << 32) | (uint64_t(1) << 16);
    return base | ((uint64_t)(addr >> 4) & 0x3FFF);
}
#define IDESC_MAIN ((1u << 4) | (1u << 7) | (1u << 10) | ((BNG / 8) << 17) | ((BMG / 16) << 24))
__device__ __forceinline__ void mma_bf16(uint32_t d, uint64_t ad, uint64_t bd, uint32_t en) {
    asm volatile(
        "{\n\t.reg .pred p;\n\tsetp.ne.u32 p, %5, 0;\n\t"
        "tcgen05.mma.cta_group::1.kind::f16 [%0], %1, %2, %3, {%4, %4, %4, %4}, p;\n\t}"
        :: "r"(d), "l"(ad), "l"(bd), "r"((uint32_t)IDESC_MAIN), "r"(0u), "r"(en) : "memory");
}
#endif

__global__ __launch_bounds__(256, 2) void gemm_fused(const void* __restrict__ xin,
                                                     const float* __restrict__ xs,
                                                     const float* __restrict__ ys,
                                                     float* __restrict__ out) {
#ifdef TC_OK
    extern __shared__ __align__(1024) uint8_t smem[];
    const uint32_t sb = smem_u32(smem);
    const int t = threadIdx.x, wid = t >> 5, lane = t & 31;
    const int z = blockIdx.z, b = z & 7;
    const int m0 = blockIdx.y * BMG;
    const int n0 = blockIdx.x * BNG;

    // inline x-format probe (uniform across block)
    int fmt = 1;
    {
        const int* xi = (const int*)xin;
        #pragma unroll
        for (int j = 0; j < 8; j++) { int v = xi[j]; fmt &= (v >= -128 && v < 128); }
    }

    // A ownership (int32 path): warp w rows 16w..16w+15
    //   inst i: row = 16w + 2i + (lane>>4), 16B chunk = (lane&15)
    const int rsel  = lane >> 4;        // 0/1
    const int off16 = lane & 15;        // 16B chunk within 256B row-segment
    // legacy ownership for raw-s8 fallback
    const int arow = t >> 1, ahalf = t & 1;
    const size_t zstride = (size_t)z * MSZ + m0;
    const uint16_t* ybp = g_ytb + (size_t)b * NSZ * KSZ + (size_t)n0 * KSZ;

    int4 r[8];   // A register staging

    auto ldgA = [&](int s) {
        if (fmt) {
            #pragma unroll
            for (int i = 0; i < 8; i++) {
                int row = wid * 16 + 2 * i + rsel;
                const int4* p = (const int4*)xin +
                    ((zstride + row) * KSZ + s * BKE) / 4 + off16;
                r[i] = *p;
            }
        } else {
            const int4* p = (const int4*)((const uint8_t*)xin +
                (zstride + arow) * KSZ + s * BKE + ahalf * 32);
            r[0] = p[0]; r[1] = p[1];
        }
    };
    auto stsA = [&](int buf) {
        uint8_t* abp = smem + SM_AB(buf);
        if (fmt) {
            #pragma unroll
            for (int i = 0; i < 8; i++) {
                int row = wid * 16 + 2 * i + rsel;
                uint2 o;
                o.x = pack_bf16((float)(r[i].x + 66), (float)(r[i].y + 66));
                o.y = pack_bf16((float)(r[i].z + 66), (float)(r[i].w + 66));
                *(uint2*)(abp + sw128(row * 128 + off16 * 8)) = o;
            }
        } else {
            #pragma unroll
            for (int j = 0; j < 4; j++) {
                uint32_t w0 = (j < 2) ? ((j & 1) ? (uint32_t)r[0].z : (uint32_t)r[0].x)
                                      : ((j & 1) ? (uint32_t)r[1].z : (uint32_t)r[1].x);
                uint32_t w1 = (j < 2) ? ((j & 1) ? (uint32_t)r[0].w : (uint32_t)r[0].y)
                                      : ((j & 1) ? (uint32_t)r[1].w : (uint32_t)r[1].y);
                uint4 o;
                o.x = pack_bf16((float)((int)(int8_t)(w0) + 66), (float)((int)(int8_t)(w0 >> 8) + 66));
                o.y = pack_bf16((float)((int)(int8_t)(w0 >> 16) + 66), (float)((int)(int8_t)(w0 >> 24) + 66));
                o.z = pack_bf16((float)((int)(int8_t)(w1) + 66), (float)((int)(int8_t)(w1 >> 8) + 66));
                o.w = pack_bf16((float)((int)(int8_t)(w1 >> 16) + 66), (float)((int)(int8_t)(w1 >> 24) + 66));
                *(uint4*)(abp + sw128(arow * 128 + (ahalf * 4 + j) * 16)) = o;
            }
        }
    };
    auto loadB = [&](int s, int buf) {
        uint32_t bbb = sb + SM_BB(buf);
        #pragma unroll
        for (int i = 0; i < 8; i++) {          // 256 rows x 128B = 2048 chunks / 256 thr
            int id = t + i * 256;
            int row = id >> 3, c = (id & 7) << 4;
            cp16(bbb + sw128(row * 128 + c),
                 (const uint8_t*)(ybp + (size_t)row * KSZ) + s * 128 + c);
        }
        asm volatile("cp.async.commit_group;" ::: "memory");
    };

    // prologue: A regs + B stage 0 in flight BEFORE (possibly blocking) alloc
    ldgA(0);
    loadB(0, 0);

    if (wid == 0) {
        asm volatile("tcgen05.alloc.cta_group::1.sync.aligned.shared::cta.b32 [%0], %1;"
                     :: "r"(sb + SM_TMEMP), "r"(256u) : "memory");
        asm volatile("tcgen05.relinquish_alloc_permit.cta_group::1.sync.aligned;" ::: "memory");
    }
    if (t == 0) { mbar_init(sb + SM_MBAR0, 1); mbar_init(sb + SM_MBAR1, 1); }
    __syncthreads();
    uint32_t tmem;
    asm volatile("ld.shared.b32 %0, [%1];" : "=r"(tmem) : "r"(sb + SM_TMEMP));

    int ph0 = 0, ph1 = 0;

    for (int s = 0; s < NSTG; s++) {
        const int buf = s & 1;
        if (s + 1 < NSTG) {
            const int nb = buf ^ 1;
            if (s + 1 >= 2) {    // nb freed when MMA(s-1) completes
                if (nb == 0) { mbar_wait(sb + SM_MBAR0, ph0); ph0 ^= 1; }
                else         { mbar_wait(sb + SM_MBAR1, ph1); ph1 ^= 1; }
            }
            loadB(s + 1, nb);
            asm volatile("cp.async.wait_group 1;" ::: "memory");   // B(s) arrived
        } else {
            asm volatile("cp.async.wait_group 0;" ::: "memory");
        }
        stsA(buf);                       // regs(s) -> swizzled bf16 A(buf)
        if (s + 1 < NSTG) ldgA(s + 1);   // prefetch next A into regs
        __syncthreads();                 // A STS + B visible to all
        asm volatile("fence.proxy.async.shared::cta;" ::: "memory");

        if (wid == 0) {
            asm volatile("tcgen05.fence::after_thread_sync;" ::: "memory");
            if (elect_one()) {
                uint64_t ad = smem_desc(sb + SM_AB(buf));
                uint64_t bd = smem_desc(sb + SM_BB(buf));
                #pragma unroll
                for (int k = 0; k < 4; k++) {   // 4 x K=16 per stage
                    mma_bf16(tmem, ad + k * 2, bd + k * 2, (uint32_t)(s * 4 + k));
                }
                asm volatile("tcgen05.commit.cta_group::1.mbarrier::arrive::one.shared::cluster.b64 [%0];"
                             :: "r"(sb + (buf ? SM_MBAR1 : SM_MBAR0)) : "memory");
            }
        }
    }

    // stage 15 committed to mbar1; covers all prior mma
    mbar_wait(sb + SM_MBAR1, ph1);
    asm volatile("tcgen05.fence::after_thread_sync;" ::: "memory");
    __syncthreads();

    // epilogue over all 8 warps: warp w reads TMEM subpartition (w&3),
    // column chunks (w>>2)*4 .. +3
    const float sc = xs[0] * ys[0];
    float* tile = (float*)(smem + wid * 4352);   // 8 x 32x33 f32 tiles (34.8KB)
    const int part = wid & 3;
    const int cbase = (wid >> 2) * 4;

    #pragma unroll 1
    for (int ci = 0; ci < 4; ci++) {
        const int chunk = cbase + ci;
        uint32_t d[32];
        asm volatile(
            "tcgen05.ld.sync.aligned.32x32b.x32.b32 "
            "{%0,%1,%2,%3,%4,%5,%6,%7,%8,%9,%10,%11,%12,%13,%14,%15,"
            "%16,%17,%18,%19,%20,%21,%22,%23,%24,%25,%26,%27,%28,%29,%30,%31}, [%32];"
            : "=r"(d[0]), "=r"(d[1]), "=r"(d[2]), "=r"(d[3]), "=r"(d[4]), "=r"(d[5]), "=r"(d[6]), "=r"(d[7]),
              "=r"(d[8]), "=r"(d[9]), "=r"(d[10]), "=r"(d[11]), "=r"(d[12]), "=r"(d[13]), "=r"(d[14]), "=r"(d[15]),
              "=r"(d[16]), "=r"(d[17]), "=r"(d[18]), "=r"(d[19]), "=r"(d[20]), "=r"(d[21]), "=r"(d[22]), "=r"(d[23]),
              "=r"(d[24]), "=r"(d[25]), "=r"(d[26]), "=r"(d[27]), "=r"(d[28]), "=r"(d[29]), "=r"(d[30]), "=r"(d[31])
            : "r"(tmem + chunk * 32));
        asm volatile("tcgen05.wait::ld.sync.aligned;" ::: "memory");

        #pragma unroll
        for (int c = 0; c < 32; c++) {
            tile[lane * 33 + c] = sc * __uint_as_float(d[c]);
        }
        __syncwarp();
        #pragma unroll
        for (int rr = 0; rr < 32; rr++) {
            out[((size_t)z * MSZ + m0 + part * 32 + rr) * NSZ + n0 + chunk * 32 + lane] = tile[rr * 33 + lane];
        }
        __syncwarp();
    }

    __syncthreads();
    if (wid == 0) {
        asm volatile("tcgen05.dealloc.cta_group::1.sync.aligned.b32 %0, %1;" :: "r"(tmem), "r"(256u));
    }
#endif
}

// ---------------------------------------------------------------------------
extern "C" void kernel_launch(void* const* d_in, const int* in_sizes, int n_in,
                              void* d_out, int out_size) {
    const void* x = nullptr;
    const void* y = nullptr;
    const float* xs = nullptr;
    const float* ys = nullptr;

    for (int i = 0; i < n_in; i++) {
        long sz = in_sizes[i];
        if (sz == (long)XELEMS) x = d_in[i];
        else if (sz == (long)YELEMS) y = d_in[i];
        else if (xs == nullptr) xs = (const float*)d_in[i];
        else if (ys == nullptr) ys = (const float*)d_in[i];
    }
    float* out = (float*)d_out;

    cudaFuncSetAttribute(gemm_fused, cudaFuncAttributeMaxDynamicSharedMemorySize, DSMEM_TC);

    transpose_y_kernel<<<dim3(NSZ / 128, KSZ / 32, BSZ), 256>>>(y);
    gemm_fused<<<dim3(NSZ / BNG, MSZ / BMG, G * BSZ), 256, DSMEM_TC>>>(x, xs, ys, out);
}